// round 6
// baseline (speedup 1.0000x reference)
#include <cuda_runtime.h>
#include <cstdint>

// ---------------- problem constants ----------------
#define NNODES 100000
#define NEDGES 1600000
#define DIN 128
#define H1 128
#define H2 64
#define NEG_SLOPE 0.2f

typedef unsigned long long ull;

// ---------------- device scratch (no allocations allowed) ----------------
static __device__ __align__(16) float g_xl[(size_t)NNODES * 128];  // current layer xl
static __device__ __align__(16) float g_h1[(size_t)NNODES * 128];  // layer-1 output
static __device__ float    g_asrc[NNODES];
static __device__ float    g_adst[NNODES];
static __device__ float    g_loopsum[NNODES];
static __device__ float    g_loopattr[NNODES];
static __device__ int      g_cnt[NNODES];       // in-degree
static __device__ int      g_rowstart[NNODES];  // CSR row offsets
static __device__ int      g_fill[NNODES];      // fill cursors
static __device__ int      g_bsum[1024];        // scan block sums
static __device__ int      g_src32[NEDGES];     // converted src indices
static __device__ int      g_dst32[NEDGES];     // converted dst indices

struct __align__(8) EdgeRec { int src; float ea; };
static __device__ EdgeRec  g_epack[NEDGES];     // CSR: (src, edge_attr) per slot
static __device__ float    g_c[2];              // dot(W_edge, att_edge) per layer
static __device__ int      g_is64;              // edge_index dtype flag

// ---------------- helpers ----------------
__device__ __forceinline__ float leaky(float x) {
    return x >= 0.f ? x : NEG_SLOPE * x;
}
__device__ __forceinline__ int clampi(int v, int lo, int hi) {
    return v < lo ? lo : (v > hi ? hi : v);
}
// packed fp32x2 FMA (SASS FFMA2) — exact fp32 on both halves, 2x issue density
__device__ __forceinline__ void fma_f32x2(ull& d, ull a, ull b, ull c) {
    asm("fma.rn.f32x2 %0, %1, %2, %3;" : "=l"(d) : "l"(a), "l"(b), "l"(c));
}
__device__ __forceinline__ ull pack_dup(float x) {
    ull r;
    asm("mov.b64 %0, {%1, %1};" : "=l"(r) : "f"(x));
    return r;
}
__device__ __forceinline__ void unpack2(float& lo, float& hi, ull v) {
    asm("mov.b64 {%0, %1}, %2;" : "=f"(lo), "=f"(hi) : "l"(v));
}

// ---------------- fused prep: zero counters / detect dtype / calc c's ----------------
// blocks [0, nbN): zero; block nbN: dtype detect; block nbN+1: c = dot(We, ae)
__global__ void prep_misc(const int* __restrict__ w,
                          const float* __restrict__ We1, const float* __restrict__ ae1,
                          const float* __restrict__ We2, const float* __restrict__ ae2,
                          int n, int nbN) {
    int b = blockIdx.x;
    if (b < nbN) {
        int i = b * blockDim.x + threadIdx.x;
        if (i < n) { g_cnt[i] = 0; g_fill[i] = 0; g_loopsum[i] = 0.f; }
        return;
    }
    if (b == nbN) {
        if (threadIdx.x < 32) {
            int any = 0;
            for (int k = threadIdx.x; k < 512; k += 32) any |= w[2 * k + 1];
            #pragma unroll
            for (int o = 16; o; o >>= 1) any |= __shfl_down_sync(0xFFFFFFFFu, any, o);
            if (threadIdx.x == 0) g_is64 = (any == 0) ? 1 : 0;
        }
        return;
    }
    // c-dots
    __shared__ float s1[128], s2[128];
    int t = threadIdx.x;
    if (t < 128) {
        s1[t] = We1[t] * ae1[t];
        s2[t] = (t < 64) ? We2[t] * ae2[t] : 0.f;
    }
    __syncthreads();
    for (int o = 64; o; o >>= 1) {
        if (t < o) { s1[t] += s1[t + o]; s2[t] += s2[t + o]; }
        __syncthreads();
    }
    if (t == 0) { g_c[0] = s1[0]; g_c[1] = s2[0]; }
}

// ---------------- fused: edge convert + degree histogram + loop attr sum ----------------
__global__ void conv_hist(const int* __restrict__ w, const float* __restrict__ ea, int E, int N) {
    int e = blockIdx.x * blockDim.x + threadIdx.x;
    if (e >= E) return;
    int s, d;
    if (g_is64) {
        const long long* w64 = (const long long*)w;
        s = (int)w64[e];
        d = (int)w64[(size_t)E + e];
    } else {
        s = w[e];
        d = w[(size_t)E + e];
    }
    s = clampi(s, 0, N - 1);
    d = clampi(d, 0, N - 1);
    g_src32[e] = s;
    g_dst32[e] = d;
    atomicAdd(&g_cnt[d], 1);
    atomicAdd(&g_loopsum[d], ea[e]);
}

// ---------------- scan1 (+ fused loop_attr) / scan2 / scan3 ----------------
__global__ void scan1(int n) {
    __shared__ int s[256];
    int t = threadIdx.x;
    int i = blockIdx.x * 256 + t;
    int v = (i < n) ? g_cnt[i] : 0;
    if (i < n) g_loopattr[i] = g_loopsum[i] / fmaxf((float)v, 1.f);
    s[t] = v;
    __syncthreads();
    #pragma unroll
    for (int o = 1; o < 256; o <<= 1) {
        int y = (t >= o) ? s[t - o] : 0;
        __syncthreads();
        s[t] += y;
        __syncthreads();
    }
    if (i < n) g_rowstart[i] = s[t] - v;   // exclusive
    if (t == 255) g_bsum[blockIdx.x] = s[255];
}
__global__ void scan2(int nb) {
    __shared__ int s[1024];
    int t = threadIdx.x;
    int v = (t < nb) ? g_bsum[t] : 0;
    s[t] = v;
    __syncthreads();
    #pragma unroll
    for (int o = 1; o < 1024; o <<= 1) {
        int y = (t >= o) ? s[t - o] : 0;
        __syncthreads();
        s[t] += y;
        __syncthreads();
    }
    if (t < nb) g_bsum[t] = s[t] - v;      // exclusive block offsets
}
__global__ void scan3(int n) {
    int i = blockIdx.x * blockDim.x + threadIdx.x;
    if (i < n) g_rowstart[i] += g_bsum[i >> 8];
}

// ---------------- CSR fill (packed records) ----------------
__global__ void csr_fill(const float* __restrict__ ea, int E) {
    int e = blockIdx.x * blockDim.x + threadIdx.x;
    if (e >= E) return;
    int d = g_dst32[e];
    int pos = g_rowstart[d] + atomicAdd(&g_fill[d], 1);
    EdgeRec r;
    r.src = g_src32[e];
    r.ea = ea[e];
    g_epack[pos] = r;
}

// ---------------- f32x2 GEMM: g_xl[N,F] = A[N,128] @ W[128,F], fused att dots ----------------
// BM=128 rows/block, BN=F (full width), BK=16. 256 threads, 8 rows x F/16 cols each.
// A tile staged PRE-DUPLICATED as (x,x) 8-byte pairs so the inner loop has zero packs.
template <int F, bool A_IS_H1>
__global__ __launch_bounds__(256) void gemm_f2(const float* __restrict__ Ain,
                                               const float* __restrict__ W,
                                               const float* __restrict__ atts,
                                               const float* __restrict__ attd,
                                               int N) {
    const float* A = A_IS_H1 ? (const float*)g_h1 : Ain;
    constexpr int BM = 128, BK = 16;
    constexpr int CJ = F / 16;    // cols per thread: 8 (F=128) or 4 (F=64)
    constexpr int CJ2 = CJ / 2;   // col pairs: 4 or 2
    __shared__ ull   As2[BK][BM];     // 16 KB: pre-duplicated A
    __shared__ float Ws[BK][F];
    const int tid = threadIdx.x;
    const int tx = tid & 15;
    const int ty = tid >> 4;
    const int row0 = blockIdx.x * BM;

    ull acc[8][CJ2];
    #pragma unroll
    for (int i = 0; i < 8; i++)
        #pragma unroll
        for (int j = 0; j < CJ2; j++) acc[i][j] = 0ull;

    for (int kb = 0; kb < 128; kb += BK) {
        // stage A chunk (BM x BK), transposed + duplicated: As2[k][r] = (a,a)
        #pragma unroll
        for (int q = 0; q < 2; q++) {
            int f4 = tid * 2 + q;
            int r = f4 >> 2, c4 = f4 & 3;
            float4 v = make_float4(0.f, 0.f, 0.f, 0.f);
            if (row0 + r < N)
                v = *(const float4*)&A[(size_t)(row0 + r) * 128 + kb + c4 * 4];
            As2[c4 * 4 + 0][r] = pack_dup(v.x);
            As2[c4 * 4 + 1][r] = pack_dup(v.y);
            As2[c4 * 4 + 2][r] = pack_dup(v.z);
            As2[c4 * 4 + 3][r] = pack_dup(v.w);
        }
        // stage W chunk (BK x F), row-major
        constexpr int NF4 = BK * F / 4;            // 512 (F=128) or 256 (F=64)
        #pragma unroll
        for (int q = 0; q < NF4 / 256; q++) {
            int f4 = tid + q * 256;
            int k = f4 / (F / 4);
            int c = (f4 % (F / 4)) * 4;
            *(float4*)&Ws[k][c] = *(const float4*)&W[(size_t)(kb + k) * F + c];
        }
        __syncthreads();
        #pragma unroll
        for (int k = 0; k < BK; k++) {
            ull a2[8];
            #pragma unroll
            for (int i = 0; i < 8; i += 2) {      // broadcast LDS.128 (ty-uniform)
                ulonglong2 av = *(const ulonglong2*)&As2[k][ty * 8 + i];
                a2[i] = av.x;
                a2[i + 1] = av.y;
            }
            ull b2[CJ2];
            #pragma unroll
            for (int j = 0; j < CJ2; j += 2) {
                ulonglong2 bv = *(const ulonglong2*)&Ws[k][tx * CJ + j * 2];
                b2[j] = bv.x;
                b2[j + 1] = bv.y;
            }
            #pragma unroll
            for (int i = 0; i < 8; i++)
                #pragma unroll
                for (int j = 0; j < CJ2; j++)
                    fma_f32x2(acc[i][j], a2[i], b2[j], acc[i][j]);
        }
        __syncthreads();
    }

    // epilogue: store C rows + fused att_src/att_dst dots
    float asv[CJ], adv[CJ];
    #pragma unroll
    for (int j = 0; j < CJ; j++) {
        asv[j] = __ldg(&atts[tx * CJ + j]);
        adv[j] = __ldg(&attd[tx * CJ + j]);
    }
    #pragma unroll
    for (int i = 0; i < 8; i++) {
        int r = row0 + ty * 8 + i;
        if (r >= N) break;
        float c8[CJ];
        #pragma unroll
        for (int j = 0; j < CJ2; j++) unpack2(c8[2 * j], c8[2 * j + 1], acc[i][j]);
        #pragma unroll
        for (int j = 0; j < CJ; j += 4) {
            float4 v = make_float4(c8[j], c8[j + 1], c8[j + 2], c8[j + 3]);
            *(float4*)&g_xl[(size_t)r * F + tx * CJ + j] = v;
        }
        float s = 0.f, d = 0.f;
        #pragma unroll
        for (int j = 0; j < CJ; j++) { s += c8[j] * asv[j]; d += c8[j] * adv[j]; }
        #pragma unroll
        for (int o = 8; o; o >>= 1) {
            s += __shfl_down_sync(0xFFFFFFFFu, s, o, 16);
            d += __shfl_down_sync(0xFFFFFFFFu, d, o, 16);
        }
        if (tx == 0) { g_asrc[r] = s; g_adst[r] = d; }
    }
}

// ---------------- fused GAT: online softmax + gather + bias + PReLU ----------------
// warp per node; lane owns F/32 consecutive floats. Reads g_xl.
template <int F, bool OUT_IS_H1>
__global__ void fused_gat(const float* __restrict__ bias, const float* __restrict__ prelu_a,
                          float* __restrict__ outp, int N, int layer) {
    int w = (blockIdx.x * blockDim.x + threadIdx.x) >> 5;
    int lane = threadIdx.x & 31;
    if (w >= N) return;
    float* out = OUT_IS_H1 ? (float*)g_h1 : outp;
    constexpr int VE = F / 32;   // 4 (F=128) or 2 (F=64)
    const float c = g_c[layer];
    const float adst = g_adst[w];
    const float lself = leaky(g_asrc[w] + adst + c * g_loopattr[w]);

    float m = lself, den = 1.f;
    float acc[VE];
    {   // self-loop contribution, p_self = 1 relative to m = lself
        const float* xr = g_xl + (size_t)w * F + lane * VE;
        if (VE == 4) {
            float4 v = *(const float4*)xr;
            acc[0] = v.x; acc[1] = v.y; acc[2] = v.z; acc[3] = v.w;
        } else {
            float2 v = *(const float2*)xr;
            acc[0] = v.x; acc[1] = v.y;
        }
    }

    const int beg = g_rowstart[w];
    const int cnt = g_cnt[w];
    for (int j = 0; j < cnt; j++) {
        EdgeRec er = g_epack[beg + j];   // 8B broadcast load (warp-uniform)
        float l = leaky(g_asrc[er.src] + adst + c * er.ea);
        const float* sr = g_xl + (size_t)er.src * F + lane * VE;
        float v[VE];
        if (VE == 4) {
            float4 t = *(const float4*)sr;
            v[0] = t.x; v[1] = t.y; v[2] = t.z; v[3] = t.w;
        } else {
            float2 t = *(const float2*)sr;
            v[0] = t.x; v[1] = t.y;
        }
        if (l <= m) {                      // common path: 1 expf, no rescale
            float p = __expf(l - m);
            den += p;
            #pragma unroll
            for (int q = 0; q < VE; q++) acc[q] += p * v[q];
        } else {                           // new max: rescale (rare, ~ln(deg) times)
            float sc = __expf(m - l);
            den = den * sc + 1.f;
            #pragma unroll
            for (int q = 0; q < VE; q++) acc[q] = acc[q] * sc + v[q];
            m = l;
        }
    }

    float inv = 1.f / den;
    float a = *prelu_a;
    #pragma unroll
    for (int q = 0; q < VE; q++) {
        float o = acc[q] * inv + bias[lane * VE + q];
        out[(size_t)w * F + lane * VE + q] = o > 0.f ? o : a * o;
    }
}

extern "C" void kernel_launch(void* const* d_in, const int* in_sizes, int n_in,
                              void* d_out, int out_size) {
    const float*      x    = (const float*)d_in[0];
    const int*        eiw  = (const int*)d_in[1];   // edge_index as 32-bit words
    const float*      ea   = (const float*)d_in[2];
    const float*      W1   = (const float*)d_in[3];
    const float*      as1  = (const float*)d_in[4];
    const float*      ad1  = (const float*)d_in[5];
    const float*      We1  = (const float*)d_in[6];
    const float*      ae1  = (const float*)d_in[7];
    const float*      b1   = (const float*)d_in[8];
    const float*      W2   = (const float*)d_in[9];
    const float*      as2  = (const float*)d_in[10];
    const float*      ad2  = (const float*)d_in[11];
    const float*      We2  = (const float*)d_in[12];
    const float*      ae2  = (const float*)d_in[13];
    const float*      b2   = (const float*)d_in[14];
    const float*      pa   = (const float*)d_in[15];
    float*            out  = (float*)d_out;

    const int N = in_sizes[0] / DIN;
    const int E = in_sizes[1] / 2;

    const int TB = 256;
    int nb_N   = (N + TB - 1) / TB;       // 391 for N=100000
    int nb_E   = (E + TB - 1) / TB;
    int nb_att = ((N * 32) + TB - 1) / TB;
    int nb_gemm = (N + 127) / 128;

    // ---- shared precompute: zero+detect+c (1 kernel), edges+degree, CSR ----
    prep_misc<<<nb_N + 2, TB>>>(eiw, We1, ae1, We2, ae2, N, nb_N);
    conv_hist<<<nb_E, TB>>>(eiw, ea, E, N);
    scan1<<<nb_N, 256>>>(N);
    scan2<<<1, 1024>>>(nb_N);
    scan3<<<nb_N, 256>>>(N);
    csr_fill<<<nb_E, TB>>>(ea, E);

    // ================= layer 1 (F = 128) =================
    gemm_f2<H1, false><<<nb_gemm, 256>>>(x, W1, as1, ad1, N);
    fused_gat<H1, true><<<nb_att, TB>>>(b1, pa, out, N, 0);

    // ================= layer 2 (F = 64) =================
    gemm_f2<H2, true><<<nb_gemm, 256>>>(nullptr, W2, as2, ad2, N);
    fused_gat<H2, false><<<nb_att, TB>>>(b2, pa, out, N, 1);
}

// round 7
// speedup vs baseline: 1.1429x; 1.1429x over previous
#include <cuda_runtime.h>
#include <cstdint>

// ---------------- problem constants ----------------
#define NNODES 100000
#define NEDGES 1600000
#define DIN 128
#define H1 128
#define H2 64
#define NEG_SLOPE 0.2f

typedef unsigned long long ull;

// ---------------- device scratch (no allocations allowed) ----------------
static __device__ __align__(16) float g_xl[(size_t)NNODES * 128];  // current layer xl
static __device__ __align__(16) float g_h1[(size_t)NNODES * 128];  // layer-1 output
static __device__ float    g_asrc[NNODES];
static __device__ float    g_adst[NNODES];
static __device__ float    g_loopsum[NNODES];
static __device__ float    g_loopattr[NNODES];
static __device__ int      g_cnt[NNODES];       // in-degree
static __device__ int      g_rowstart[NNODES];  // CSR row offsets (pre block-offset)
static __device__ int      g_fill[NNODES];      // fill cursors
static __device__ int      g_bsum[1024];        // scan block sums

struct __align__(8) EdgeRec { int src; float ea; };
static __device__ EdgeRec  g_epack[NEDGES];     // CSR: (src, edge_attr) per slot
static __device__ float    g_c[2];              // dot(W_edge, att_edge) per layer
static __device__ int      g_is64;              // edge_index dtype flag

// ---------------- helpers ----------------
__device__ __forceinline__ float leaky(float x) {
    return x >= 0.f ? x : NEG_SLOPE * x;
}
__device__ __forceinline__ int clampi(int v, int lo, int hi) {
    return v < lo ? lo : (v > hi ? hi : v);
}
// packed fp32x2 FMA (SASS FFMA2) — exact fp32 on both halves, 2x issue density
__device__ __forceinline__ void fma_f32x2(ull& d, ull a, ull b, ull c) {
    asm("fma.rn.f32x2 %0, %1, %2, %3;" : "=l"(d) : "l"(a), "l"(b), "l"(c));
}
__device__ __forceinline__ ull pack_dup(float x) {
    ull r;
    asm("mov.b64 %0, {%1, %1};" : "=l"(r) : "f"(x));
    return r;
}
__device__ __forceinline__ void unpack2(float& lo, float& hi, ull v) {
    asm("mov.b64 {%0, %1}, %2;" : "=f"(lo), "=f"(hi) : "l"(v));
}

// ---------------- fused prep: zero counters / detect dtype / calc c's ----------------
__global__ void prep_misc(const int* __restrict__ w,
                          const float* __restrict__ We1, const float* __restrict__ ae1,
                          const float* __restrict__ We2, const float* __restrict__ ae2,
                          int n, int nbN) {
    int b = blockIdx.x;
    if (b < nbN) {
        int i = b * blockDim.x + threadIdx.x;
        if (i < n) { g_cnt[i] = 0; g_fill[i] = 0; g_loopsum[i] = 0.f; }
        return;
    }
    if (b == nbN) {
        if (threadIdx.x < 32) {
            int any = 0;
            for (int k = threadIdx.x; k < 512; k += 32) any |= w[2 * k + 1];
            #pragma unroll
            for (int o = 16; o; o >>= 1) any |= __shfl_down_sync(0xFFFFFFFFu, any, o);
            if (threadIdx.x == 0) g_is64 = (any == 0) ? 1 : 0;
        }
        return;
    }
    // c-dots
    __shared__ float s1[128], s2[128];
    int t = threadIdx.x;
    if (t < 128) {
        s1[t] = We1[t] * ae1[t];
        s2[t] = (t < 64) ? We2[t] * ae2[t] : 0.f;
    }
    __syncthreads();
    for (int o = 64; o; o >>= 1) {
        if (t < o) { s1[t] += s1[t + o]; s2[t] += s2[t + o]; }
        __syncthreads();
    }
    if (t == 0) { g_c[0] = s1[0]; g_c[1] = s2[0]; }
}

// ---------------- edge decode (shared by conv_hist / csr_fill) ----------------
__device__ __forceinline__ void decode_edge(const int* __restrict__ w, int e, int E, int N,
                                            int& s, int& d) {
    if (g_is64) {
        const long long* w64 = (const long long*)w;
        s = (int)w64[e];
        d = (int)w64[(size_t)E + e];
    } else {
        s = w[e];
        d = w[(size_t)E + e];
    }
    s = clampi(s, 0, N - 1);
    d = clampi(d, 0, N - 1);
}

// ---------------- degree histogram + loop attr sum ----------------
__global__ void conv_hist(const int* __restrict__ w, const float* __restrict__ ea, int E, int N) {
    int e = blockIdx.x * blockDim.x + threadIdx.x;
    if (e >= E) return;
    int s, d;
    decode_edge(w, e, E, N, s, d);
    atomicAdd(&g_cnt[d], 1);
    atomicAdd(&g_loopsum[d], ea[e]);
}

// ---------------- scan1 (+ fused loop_attr) / scan2 ----------------
__global__ void scan1(int n) {
    __shared__ int s[256];
    int t = threadIdx.x;
    int i = blockIdx.x * 256 + t;
    int v = (i < n) ? g_cnt[i] : 0;
    if (i < n) g_loopattr[i] = g_loopsum[i] / fmaxf((float)v, 1.f);
    s[t] = v;
    __syncthreads();
    #pragma unroll
    for (int o = 1; o < 256; o <<= 1) {
        int y = (t >= o) ? s[t - o] : 0;
        __syncthreads();
        s[t] += y;
        __syncthreads();
    }
    if (i < n) g_rowstart[i] = s[t] - v;   // exclusive, pre block-offset
    if (t == 255) g_bsum[blockIdx.x] = s[255];
}
__global__ void scan2(int nb) {
    __shared__ int s[1024];
    int t = threadIdx.x;
    int v = (t < nb) ? g_bsum[t] : 0;
    s[t] = v;
    __syncthreads();
    #pragma unroll
    for (int o = 1; o < 1024; o <<= 1) {
        int y = (t >= o) ? s[t - o] : 0;
        __syncthreads();
        s[t] += y;
        __syncthreads();
    }
    if (t < nb) g_bsum[t] = s[t] - v;      // exclusive block offsets
}

// ---------------- CSR fill (decodes edges directly, adds block offset) ----------------
__global__ void csr_fill(const int* __restrict__ w, const float* __restrict__ ea, int E, int N) {
    int e = blockIdx.x * blockDim.x + threadIdx.x;
    if (e >= E) return;
    int s, d;
    decode_edge(w, e, E, N, s, d);
    int pos = g_rowstart[d] + g_bsum[d >> 8] + atomicAdd(&g_fill[d], 1);
    EdgeRec r;
    r.src = s;
    r.ea = ea[e];
    g_epack[pos] = r;
}

// ---------------- f32x2 GEMM: g_xl[N,F] = A[N,128] @ W[128,F], fused att dots ----------------
// Round-5 proven form: BM=128, BN=F, BK=16; packs in registers, 8KB As + Ws.
template <int F, bool A_IS_H1>
__global__ __launch_bounds__(256) void gemm_f2(const float* __restrict__ Ain,
                                               const float* __restrict__ W,
                                               const float* __restrict__ atts,
                                               const float* __restrict__ attd,
                                               int N) {
    const float* A = A_IS_H1 ? (const float*)g_h1 : Ain;
    constexpr int BM = 128, BK = 16;
    constexpr int CJ = F / 16;    // cols per thread: 8 (F=128) or 4 (F=64)
    constexpr int CJ2 = CJ / 2;   // col pairs: 4 or 2
    __shared__ float As[BK][BM];
    __shared__ float Ws[BK][F];
    const int tid = threadIdx.x;
    const int tx = tid & 15;
    const int ty = tid >> 4;
    const int row0 = blockIdx.x * BM;

    ull acc[8][CJ2];
    #pragma unroll
    for (int i = 0; i < 8; i++)
        #pragma unroll
        for (int j = 0; j < CJ2; j++) acc[i][j] = 0ull;

    for (int kb = 0; kb < 128; kb += BK) {
        // stage A chunk (BM x BK), transposed: As[k][r]
        #pragma unroll
        for (int q = 0; q < 2; q++) {
            int f4 = tid * 2 + q;
            int r = f4 >> 2, c4 = f4 & 3;
            float4 v = make_float4(0.f, 0.f, 0.f, 0.f);
            if (row0 + r < N)
                v = *(const float4*)&A[(size_t)(row0 + r) * 128 + kb + c4 * 4];
            As[c4 * 4 + 0][r] = v.x;
            As[c4 * 4 + 1][r] = v.y;
            As[c4 * 4 + 2][r] = v.z;
            As[c4 * 4 + 3][r] = v.w;
        }
        // stage W chunk (BK x F), row-major
        constexpr int NF4 = BK * F / 4;            // 512 (F=128) or 256 (F=64)
        #pragma unroll
        for (int q = 0; q < NF4 / 256; q++) {
            int f4 = tid + q * 256;
            int k = f4 / (F / 4);
            int c = (f4 % (F / 4)) * 4;
            *(float4*)&Ws[k][c] = *(const float4*)&W[(size_t)(kb + k) * F + c];
        }
        __syncthreads();
        #pragma unroll
        for (int k = 0; k < BK; k++) {
            float4 a0 = *(const float4*)&As[k][ty * 8];
            float4 a1 = *(const float4*)&As[k][ty * 8 + 4];
            ull a2[8];
            a2[0] = pack_dup(a0.x); a2[1] = pack_dup(a0.y);
            a2[2] = pack_dup(a0.z); a2[3] = pack_dup(a0.w);
            a2[4] = pack_dup(a1.x); a2[5] = pack_dup(a1.y);
            a2[6] = pack_dup(a1.z); a2[7] = pack_dup(a1.w);
            ull b2[CJ2];
            #pragma unroll
            for (int j = 0; j < CJ2; j += 2) {
                ulonglong2 bv = *(const ulonglong2*)&Ws[k][tx * CJ + j * 2];
                b2[j] = bv.x;
                b2[j + 1] = bv.y;
            }
            #pragma unroll
            for (int i = 0; i < 8; i++)
                #pragma unroll
                for (int j = 0; j < CJ2; j++)
                    fma_f32x2(acc[i][j], a2[i], b2[j], acc[i][j]);
        }
        __syncthreads();
    }

    // epilogue: store C rows + fused att_src/att_dst dots
    float asv[CJ], adv[CJ];
    #pragma unroll
    for (int j = 0; j < CJ; j++) {
        asv[j] = __ldg(&atts[tx * CJ + j]);
        adv[j] = __ldg(&attd[tx * CJ + j]);
    }
    #pragma unroll
    for (int i = 0; i < 8; i++) {
        int r = row0 + ty * 8 + i;
        if (r >= N) break;
        float c8[CJ];
        #pragma unroll
        for (int j = 0; j < CJ2; j++) unpack2(c8[2 * j], c8[2 * j + 1], acc[i][j]);
        #pragma unroll
        for (int j = 0; j < CJ; j += 4) {
            float4 v = make_float4(c8[j], c8[j + 1], c8[j + 2], c8[j + 3]);
            *(float4*)&g_xl[(size_t)r * F + tx * CJ + j] = v;
        }
        float s = 0.f, d = 0.f;
        #pragma unroll
        for (int j = 0; j < CJ; j++) { s += c8[j] * asv[j]; d += c8[j] * adv[j]; }
        #pragma unroll
        for (int o = 8; o; o >>= 1) {
            s += __shfl_down_sync(0xFFFFFFFFu, s, o, 16);
            d += __shfl_down_sync(0xFFFFFFFFu, d, o, 16);
        }
        if (tx == 0) { g_asrc[r] = s; g_adst[r] = d; }
    }
}

// ---------------- fused GAT: online softmax + gather + bias + PReLU ----------------
// warp per node; lane owns F/32 consecutive floats. Reads g_xl.
template <int F, bool OUT_IS_H1>
__global__ void fused_gat(const float* __restrict__ bias, const float* __restrict__ prelu_a,
                          float* __restrict__ outp, int N, int layer) {
    int w = (blockIdx.x * blockDim.x + threadIdx.x) >> 5;
    int lane = threadIdx.x & 31;
    if (w >= N) return;
    float* out = OUT_IS_H1 ? (float*)g_h1 : outp;
    constexpr int VE = F / 32;   // 4 (F=128) or 2 (F=64)
    const float c = g_c[layer];
    const float adst = g_adst[w];
    const float lself = leaky(g_asrc[w] + adst + c * g_loopattr[w]);

    float m = lself, den = 1.f;
    float acc[VE];
    {   // self-loop contribution, p_self = 1 relative to m = lself
        const float* xr = g_xl + (size_t)w * F + lane * VE;
        if (VE == 4) {
            float4 v = *(const float4*)xr;
            acc[0] = v.x; acc[1] = v.y; acc[2] = v.z; acc[3] = v.w;
        } else {
            float2 v = *(const float2*)xr;
            acc[0] = v.x; acc[1] = v.y;
        }
    }

    const int beg = g_rowstart[w] + g_bsum[w >> 8];
    const int cnt = g_cnt[w];
    for (int j = 0; j < cnt; j++) {
        EdgeRec er = g_epack[beg + j];   // 8B broadcast load (warp-uniform)
        float l = leaky(g_asrc[er.src] + adst + c * er.ea);
        const float* sr = g_xl + (size_t)er.src * F + lane * VE;
        float v[VE];
        if (VE == 4) {
            float4 t = *(const float4*)sr;
            v[0] = t.x; v[1] = t.y; v[2] = t.z; v[3] = t.w;
        } else {
            float2 t = *(const float2*)sr;
            v[0] = t.x; v[1] = t.y;
        }
        if (l <= m) {                      // common path: 1 expf, no rescale
            float p = __expf(l - m);
            den += p;
            #pragma unroll
            for (int q = 0; q < VE; q++) acc[q] += p * v[q];
        } else {                           // new max: rescale (rare, ~ln(deg) times)
            float sc = __expf(m - l);
            den = den * sc + 1.f;
            #pragma unroll
            for (int q = 0; q < VE; q++) acc[q] = acc[q] * sc + v[q];
            m = l;
        }
    }

    float inv = 1.f / den;
    float a = *prelu_a;
    #pragma unroll
    for (int q = 0; q < VE; q++) {
        float o = acc[q] * inv + bias[lane * VE + q];
        out[(size_t)w * F + lane * VE + q] = o > 0.f ? o : a * o;
    }
}

extern "C" void kernel_launch(void* const* d_in, const int* in_sizes, int n_in,
                              void* d_out, int out_size) {
    const float*      x    = (const float*)d_in[0];
    const int*        eiw  = (const int*)d_in[1];   // edge_index as 32-bit words
    const float*      ea   = (const float*)d_in[2];
    const float*      W1   = (const float*)d_in[3];
    const float*      as1  = (const float*)d_in[4];
    const float*      ad1  = (const float*)d_in[5];
    const float*      We1  = (const float*)d_in[6];
    const float*      ae1  = (const float*)d_in[7];
    const float*      b1   = (const float*)d_in[8];
    const float*      W2   = (const float*)d_in[9];
    const float*      as2  = (const float*)d_in[10];
    const float*      ad2  = (const float*)d_in[11];
    const float*      We2  = (const float*)d_in[12];
    const float*      ae2  = (const float*)d_in[13];
    const float*      b2   = (const float*)d_in[14];
    const float*      pa   = (const float*)d_in[15];
    float*            out  = (float*)d_out;

    const int N = in_sizes[0] / DIN;
    const int E = in_sizes[1] / 2;

    const int TB = 256;
    int nb_N   = (N + TB - 1) / TB;       // 391 for N=100000
    int nb_E   = (E + TB - 1) / TB;
    int nb_att = ((N * 32) + TB - 1) / TB;
    int nb_gemm = (N + 127) / 128;

    // ---- prep: zero+detect+c, histogram, scan x2, CSR fill (5 launches) ----
    prep_misc<<<nb_N + 2, TB>>>(eiw, We1, ae1, We2, ae2, N, nb_N);
    conv_hist<<<nb_E, TB>>>(eiw, ea, E, N);
    scan1<<<nb_N, 256>>>(N);
    scan2<<<1, 1024>>>(nb_N);
    csr_fill<<<nb_E, TB>>>(eiw, ea, E, N);

    // ================= layer 1 (F = 128) ================= (gemm is launch #6 -> profiled)
    gemm_f2<H1, false><<<nb_gemm, 256>>>(x, W1, as1, ad1, N);
    fused_gat<H1, true><<<nb_att, TB>>>(b1, pa, out, N, 0);

    // ================= layer 2 (F = 64) =================
    gemm_f2<H2, true><<<nb_gemm, 256>>>(nullptr, W2, as2, ad2, N);
    fused_gat<H2, false><<<nb_att, TB>>>(b2, pa, out, N, 1);
}

// round 8
// speedup vs baseline: 1.1912x; 1.0423x over previous
#include <cuda_runtime.h>
#include <cuda_fp16.h>
#include <cstdint>

// ---------------- problem constants ----------------
#define NNODES 100000
#define NEDGES 1600000
#define DIN 128
#define H1 128
#define H2 64
#define NEG_SLOPE 0.2f

typedef unsigned long long ull;

// ---------------- device scratch (no allocations allowed) ----------------
static __device__ __align__(16) __half g_xh[(size_t)NNODES * 128]; // fp16 xl (gather source)
static __device__ __align__(16) float  g_h1[(size_t)NNODES * 128]; // layer-1 output (fp32)
static __device__ float    g_asrc[NNODES];
static __device__ float    g_adst[NNODES];
static __device__ float    g_loopsum[NNODES];
static __device__ float    g_loopattr[NNODES];
static __device__ int      g_cnt[NNODES];       // in-degree
static __device__ int      g_rowstart[NNODES];  // CSR row offsets (pre block-offset)
static __device__ int      g_fill[NNODES];      // fill cursors
static __device__ int      g_bsum[1024];        // scan block sums

struct __align__(8) EdgeRec { int src; float ea; };
static __device__ EdgeRec  g_epack[NEDGES];     // CSR: (src, edge_attr) per slot
static __device__ float    g_c[2];              // dot(W_edge, att_edge) per layer
static __device__ int      g_is64;              // edge_index dtype flag

// ---------------- helpers ----------------
__device__ __forceinline__ float leaky(float x) {
    return x >= 0.f ? x : NEG_SLOPE * x;
}
__device__ __forceinline__ int clampi(int v, int lo, int hi) {
    return v < lo ? lo : (v > hi ? hi : v);
}
// packed fp32x2 FMA (SASS FFMA2) — exact fp32 on both halves, 2x issue density
__device__ __forceinline__ void fma_f32x2(ull& d, ull a, ull b, ull c) {
    asm("fma.rn.f32x2 %0, %1, %2, %3;" : "=l"(d) : "l"(a), "l"(b), "l"(c));
}
__device__ __forceinline__ ull pack_dup(float x) {
    ull r;
    asm("mov.b64 %0, {%1, %1};" : "=l"(r) : "f"(x));
    return r;
}
__device__ __forceinline__ void unpack2(float& lo, float& hi, ull v) {
    asm("mov.b64 {%0, %1}, %2;" : "=f"(lo), "=f"(hi) : "l"(v));
}

// ---------------- fused prep: zero counters / detect dtype / calc c's ----------------
__global__ void prep_misc(const int* __restrict__ w,
                          const float* __restrict__ We1, const float* __restrict__ ae1,
                          const float* __restrict__ We2, const float* __restrict__ ae2,
                          int n, int nbN) {
    int b = blockIdx.x;
    if (b < nbN) {
        int i = b * blockDim.x + threadIdx.x;
        if (i < n) { g_cnt[i] = 0; g_fill[i] = 0; g_loopsum[i] = 0.f; }
        return;
    }
    if (b == nbN) {
        if (threadIdx.x < 32) {
            int any = 0;
            for (int k = threadIdx.x; k < 512; k += 32) any |= w[2 * k + 1];
            #pragma unroll
            for (int o = 16; o; o >>= 1) any |= __shfl_down_sync(0xFFFFFFFFu, any, o);
            if (threadIdx.x == 0) g_is64 = (any == 0) ? 1 : 0;
        }
        return;
    }
    // c-dots
    __shared__ float s1[128], s2[128];
    int t = threadIdx.x;
    if (t < 128) {
        s1[t] = We1[t] * ae1[t];
        s2[t] = (t < 64) ? We2[t] * ae2[t] : 0.f;
    }
    __syncthreads();
    for (int o = 64; o; o >>= 1) {
        if (t < o) { s1[t] += s1[t + o]; s2[t] += s2[t + o]; }
        __syncthreads();
    }
    if (t == 0) { g_c[0] = s1[0]; g_c[1] = s2[0]; }
}

// ---------------- edge decode (shared by conv_hist / csr_fill) ----------------
__device__ __forceinline__ void decode_edge(const int* __restrict__ w, int e, int E, int N,
                                            int& s, int& d) {
    if (g_is64) {
        const long long* w64 = (const long long*)w;
        s = (int)w64[e];
        d = (int)w64[(size_t)E + e];
    } else {
        s = w[e];
        d = w[(size_t)E + e];
    }
    s = clampi(s, 0, N - 1);
    d = clampi(d, 0, N - 1);
}

// ---------------- degree histogram + loop attr sum ----------------
__global__ void conv_hist(const int* __restrict__ w, const float* __restrict__ ea, int E, int N) {
    int e = blockIdx.x * blockDim.x + threadIdx.x;
    if (e >= E) return;
    int s, d;
    decode_edge(w, e, E, N, s, d);
    atomicAdd(&g_cnt[d], 1);
    atomicAdd(&g_loopsum[d], ea[e]);
}

// ---------------- scan1 (+ fused loop_attr) / scan2 ----------------
__global__ void scan1(int n) {
    __shared__ int s[256];
    int t = threadIdx.x;
    int i = blockIdx.x * 256 + t;
    int v = (i < n) ? g_cnt[i] : 0;
    if (i < n) g_loopattr[i] = g_loopsum[i] / fmaxf((float)v, 1.f);
    s[t] = v;
    __syncthreads();
    #pragma unroll
    for (int o = 1; o < 256; o <<= 1) {
        int y = (t >= o) ? s[t - o] : 0;
        __syncthreads();
        s[t] += y;
        __syncthreads();
    }
    if (i < n) g_rowstart[i] = s[t] - v;   // exclusive, pre block-offset
    if (t == 255) g_bsum[blockIdx.x] = s[255];
}
__global__ void scan2(int nb) {
    __shared__ int s[1024];
    int t = threadIdx.x;
    int v = (t < nb) ? g_bsum[t] : 0;
    s[t] = v;
    __syncthreads();
    #pragma unroll
    for (int o = 1; o < 1024; o <<= 1) {
        int y = (t >= o) ? s[t - o] : 0;
        __syncthreads();
        s[t] += y;
        __syncthreads();
    }
    if (t < nb) g_bsum[t] = s[t] - v;      // exclusive block offsets
}

// ---------------- CSR fill (decodes edges directly, adds block offset) ----------------
__global__ void csr_fill(const int* __restrict__ w, const float* __restrict__ ea, int E, int N) {
    int e = blockIdx.x * blockDim.x + threadIdx.x;
    if (e >= E) return;
    int s, d;
    decode_edge(w, e, E, N, s, d);
    int pos = g_rowstart[d] + g_bsum[d >> 8] + atomicAdd(&g_fill[d], 1);
    EdgeRec r;
    r.src = s;
    r.ea = ea[e];
    g_epack[pos] = r;
}

// ---------------- f32x2 GEMM: g_xh[N,F] = half(A[N,128] @ W[128,F]), fused att dots ----------------
// Round-5 proven mainloop; epilogue computes fp32 att dots, then stores fp16 features.
template <int F, bool A_IS_H1>
__global__ __launch_bounds__(256) void gemm_f2(const float* __restrict__ Ain,
                                               const float* __restrict__ W,
                                               const float* __restrict__ atts,
                                               const float* __restrict__ attd,
                                               int N) {
    const float* A = A_IS_H1 ? (const float*)g_h1 : Ain;
    constexpr int BM = 128, BK = 16;
    constexpr int CJ = F / 16;    // cols per thread: 8 (F=128) or 4 (F=64)
    constexpr int CJ2 = CJ / 2;   // col pairs: 4 or 2
    __shared__ float As[BK][BM];
    __shared__ float Ws[BK][F];
    const int tid = threadIdx.x;
    const int tx = tid & 15;
    const int ty = tid >> 4;
    const int row0 = blockIdx.x * BM;

    ull acc[8][CJ2];
    #pragma unroll
    for (int i = 0; i < 8; i++)
        #pragma unroll
        for (int j = 0; j < CJ2; j++) acc[i][j] = 0ull;

    for (int kb = 0; kb < 128; kb += BK) {
        // stage A chunk (BM x BK), transposed: As[k][r]
        #pragma unroll
        for (int q = 0; q < 2; q++) {
            int f4 = tid * 2 + q;
            int r = f4 >> 2, c4 = f4 & 3;
            float4 v = make_float4(0.f, 0.f, 0.f, 0.f);
            if (row0 + r < N)
                v = *(const float4*)&A[(size_t)(row0 + r) * 128 + kb + c4 * 4];
            As[c4 * 4 + 0][r] = v.x;
            As[c4 * 4 + 1][r] = v.y;
            As[c4 * 4 + 2][r] = v.z;
            As[c4 * 4 + 3][r] = v.w;
        }
        // stage W chunk (BK x F), row-major
        constexpr int NF4 = BK * F / 4;            // 512 (F=128) or 256 (F=64)
        #pragma unroll
        for (int q = 0; q < NF4 / 256; q++) {
            int f4 = tid + q * 256;
            int k = f4 / (F / 4);
            int c = (f4 % (F / 4)) * 4;
            *(float4*)&Ws[k][c] = *(const float4*)&W[(size_t)(kb + k) * F + c];
        }
        __syncthreads();
        #pragma unroll
        for (int k = 0; k < BK; k++) {
            float4 a0 = *(const float4*)&As[k][ty * 8];
            float4 a1 = *(const float4*)&As[k][ty * 8 + 4];
            ull a2[8];
            a2[0] = pack_dup(a0.x); a2[1] = pack_dup(a0.y);
            a2[2] = pack_dup(a0.z); a2[3] = pack_dup(a0.w);
            a2[4] = pack_dup(a1.x); a2[5] = pack_dup(a1.y);
            a2[6] = pack_dup(a1.z); a2[7] = pack_dup(a1.w);
            ull b2[CJ2];
            #pragma unroll
            for (int j = 0; j < CJ2; j += 2) {
                ulonglong2 bv = *(const ulonglong2*)&Ws[k][tx * CJ + j * 2];
                b2[j] = bv.x;
                b2[j + 1] = bv.y;
            }
            #pragma unroll
            for (int i = 0; i < 8; i++)
                #pragma unroll
                for (int j = 0; j < CJ2; j++)
                    fma_f32x2(acc[i][j], a2[i], b2[j], acc[i][j]);
        }
        __syncthreads();
    }

    // epilogue: fp32 att dots + fp16 feature store
    float asv[CJ], adv[CJ];
    #pragma unroll
    for (int j = 0; j < CJ; j++) {
        asv[j] = __ldg(&atts[tx * CJ + j]);
        adv[j] = __ldg(&attd[tx * CJ + j]);
    }
    #pragma unroll
    for (int i = 0; i < 8; i++) {
        int r = row0 + ty * 8 + i;
        if (r >= N) break;
        float c8[CJ];
        #pragma unroll
        for (int j = 0; j < CJ2; j++) unpack2(c8[2 * j], c8[2 * j + 1], acc[i][j]);
        // att dots from full-precision fp32 values
        float s = 0.f, d = 0.f;
        #pragma unroll
        for (int j = 0; j < CJ; j++) { s += c8[j] * asv[j]; d += c8[j] * adv[j]; }
        #pragma unroll
        for (int o = 8; o; o >>= 1) {
            s += __shfl_down_sync(0xFFFFFFFFu, s, o, 16);
            d += __shfl_down_sync(0xFFFFFFFFu, d, o, 16);
        }
        if (tx == 0) { g_asrc[r] = s; g_adst[r] = d; }
        // fp16 store
        uint32_t hw[CJ2];
        #pragma unroll
        for (int j = 0; j < CJ2; j++) {
            __half2 h = __floats2half2_rn(c8[2 * j], c8[2 * j + 1]);
            hw[j] = *(uint32_t*)&h;
        }
        __half* dst = &g_xh[(size_t)r * F + tx * CJ];
        if (CJ2 == 4) *(uint4*)dst = make_uint4(hw[0], hw[1], hw[2], hw[3]);
        else          *(uint2*)dst = make_uint2(hw[0], hw[1]);
    }
}

// ---------------- fused GAT: online softmax + fp16 gather + bias + PReLU ----------------
// warp per node; lane owns F/32 consecutive features. Reads g_xh (fp16), fp32 accum.
template <int F, bool OUT_IS_H1>
__global__ void fused_gat(const float* __restrict__ bias, const float* __restrict__ prelu_a,
                          float* __restrict__ outp, int N, int layer) {
    int w = (blockIdx.x * blockDim.x + threadIdx.x) >> 5;
    int lane = threadIdx.x & 31;
    if (w >= N) return;
    float* out = OUT_IS_H1 ? (float*)g_h1 : outp;
    constexpr int VE = F / 32;   // 4 (F=128) or 2 (F=64)
    const float c = g_c[layer];
    const float adst = g_adst[w];
    const float lself = leaky(g_asrc[w] + adst + c * g_loopattr[w]);

    float m = lself, den = 1.f;
    float acc[VE];
    {   // self-loop contribution, p_self = 1 relative to m = lself
        const __half* xr = g_xh + (size_t)w * F + lane * VE;
        if (VE == 4) {
            uint2 u = *(const uint2*)xr;
            float2 f0 = __half22float2(*(const __half2*)&u.x);
            float2 f1 = __half22float2(*(const __half2*)&u.y);
            acc[0] = f0.x; acc[1] = f0.y; acc[2] = f1.x; acc[3] = f1.y;
        } else {
            uint32_t u = *(const uint32_t*)xr;
            float2 f0 = __half22float2(*(const __half2*)&u);
            acc[0] = f0.x; acc[1] = f0.y;
        }
    }

    const int beg = g_rowstart[w] + g_bsum[w >> 8];
    const int cnt = g_cnt[w];
    for (int j = 0; j < cnt; j++) {
        EdgeRec er = g_epack[beg + j];   // 8B broadcast load (warp-uniform)
        float l = leaky(g_asrc[er.src] + adst + c * er.ea);
        const __half* sr = g_xh + (size_t)er.src * F + lane * VE;
        float v[VE];
        if (VE == 4) {
            uint2 u = *(const uint2*)sr;
            float2 f0 = __half22float2(*(const __half2*)&u.x);
            float2 f1 = __half22float2(*(const __half2*)&u.y);
            v[0] = f0.x; v[1] = f0.y; v[2] = f1.x; v[3] = f1.y;
        } else {
            uint32_t u = *(const uint32_t*)sr;
            float2 f0 = __half22float2(*(const __half2*)&u);
            v[0] = f0.x; v[1] = f0.y;
        }
        if (l <= m) {                      // common path: 1 expf, no rescale
            float p = __expf(l - m);
            den += p;
            #pragma unroll
            for (int q = 0; q < VE; q++) acc[q] += p * v[q];
        } else {                           // new max: rescale (rare, ~ln(deg) times)
            float sc = __expf(m - l);
            den = den * sc + 1.f;
            #pragma unroll
            for (int q = 0; q < VE; q++) acc[q] = acc[q] * sc + v[q];
            m = l;
        }
    }

    float inv = 1.f / den;
    float a = *prelu_a;
    #pragma unroll
    for (int q = 0; q < VE; q++) {
        float o = acc[q] * inv + bias[lane * VE + q];
        out[(size_t)w * F + lane * VE + q] = o > 0.f ? o : a * o;
    }
}

extern "C" void kernel_launch(void* const* d_in, const int* in_sizes, int n_in,
                              void* d_out, int out_size) {
    const float*      x    = (const float*)d_in[0];
    const int*        eiw  = (const int*)d_in[1];   // edge_index as 32-bit words
    const float*      ea   = (const float*)d_in[2];
    const float*      W1   = (const float*)d_in[3];
    const float*      as1  = (const float*)d_in[4];
    const float*      ad1  = (const float*)d_in[5];
    const float*      We1  = (const float*)d_in[6];
    const float*      ae1  = (const float*)d_in[7];
    const float*      b1   = (const float*)d_in[8];
    const float*      W2   = (const float*)d_in[9];
    const float*      as2  = (const float*)d_in[10];
    const float*      ad2  = (const float*)d_in[11];
    const float*      We2  = (const float*)d_in[12];
    const float*      ae2  = (const float*)d_in[13];
    const float*      b2   = (const float*)d_in[14];
    const float*      pa   = (const float*)d_in[15];
    float*            out  = (float*)d_out;

    const int N = in_sizes[0] / DIN;
    const int E = in_sizes[1] / 2;

    const int TB = 256;
    int nb_N   = (N + TB - 1) / TB;       // 391 for N=100000
    int nb_E   = (E + TB - 1) / TB;
    int nb_att = ((N * 32) + TB - 1) / TB;
    int nb_gemm = (N + 127) / 128;

    // ---- prep: zero+detect+c, histogram, scan x2, CSR fill (5 launches) ----
    prep_misc<<<nb_N + 2, TB>>>(eiw, We1, ae1, We2, ae2, N, nb_N);
    conv_hist<<<nb_E, TB>>>(eiw, ea, E, N);
    scan1<<<nb_N, 256>>>(N);
    scan2<<<1, 1024>>>(nb_N);
    csr_fill<<<nb_E, TB>>>(eiw, ea, E, N);

    // ================= layer 1 (F = 128) =================
    gemm_f2<H1, false><<<nb_gemm, 256>>>(x, W1, as1, ad1, N);
    fused_gat<H1, true><<<nb_att, TB>>>(b1, pa, out, N, 0);

    // ================= layer 2 (F = 64) =================
    gemm_f2<H2, true><<<nb_gemm, 256>>>(nullptr, W2, as2, ad2, N);
    fused_gat<H2, false><<<nb_att, TB>>>(b2, pa, out, N, 1);
}

// round 9
// speedup vs baseline: 1.2342x; 1.0361x over previous
#include <cuda_runtime.h>
#include <cuda_fp16.h>
#include <cstdint>

// ---------------- problem constants ----------------
#define NNODES 100000
#define NEDGES 1600000
#define DIN 128
#define H1 128
#define H2 64
#define NEG_SLOPE 0.2f

typedef unsigned long long ull;

// ---------------- device scratch (no allocations allowed) ----------------
static __device__ __align__(16) __half g_xh[(size_t)NNODES * 128]; // fp16 xl (gather source)
static __device__ __align__(16) float  g_h1[(size_t)NNODES * 128]; // layer-1 output (fp32)
static __device__ float    g_asrc[NNODES];
static __device__ float    g_adst[NNODES];
static __device__ float    g_loopsum[NNODES];
static __device__ float    g_loopattr[NNODES];
static __device__ int      g_cnt[NNODES];       // in-degree
static __device__ int      g_rowstart[NNODES];  // CSR row offsets (pre block-offset)
static __device__ int      g_fill[NNODES];      // fill cursors
static __device__ int      g_bsum[1024];        // scan block sums

struct __align__(8) EdgeRec { int src; float ea; };
static __device__ EdgeRec  g_epack[NEDGES];     // CSR: (src, edge_attr) per slot
static __device__ float    g_c[2];              // dot(W_edge, att_edge) per layer
static __device__ int      g_is64;              // edge_index dtype flag

// ---------------- helpers ----------------
__device__ __forceinline__ float leaky(float x) {
    return x >= 0.f ? x : NEG_SLOPE * x;
}
__device__ __forceinline__ int clampi(int v, int lo, int hi) {
    return v < lo ? lo : (v > hi ? hi : v);
}
// packed fp32x2 FMA (SASS FFMA2) — exact fp32 on both halves, 2x issue density
__device__ __forceinline__ void fma_f32x2(ull& d, ull a, ull b, ull c) {
    asm("fma.rn.f32x2 %0, %1, %2, %3;" : "=l"(d) : "l"(a), "l"(b), "l"(c));
}
__device__ __forceinline__ ull pack_dup(float x) {
    ull r;
    asm("mov.b64 %0, {%1, %1};" : "=l"(r) : "f"(x));
    return r;
}
__device__ __forceinline__ void unpack2(float& lo, float& hi, ull v) {
    asm("mov.b64 {%0, %1}, %2;" : "=f"(lo), "=f"(hi) : "l"(v));
}

// ---------------- fused prep: zero counters / detect dtype / calc c's ----------------
__global__ void prep_misc(const int* __restrict__ w,
                          const float* __restrict__ We1, const float* __restrict__ ae1,
                          const float* __restrict__ We2, const float* __restrict__ ae2,
                          int n, int nbN) {
    int b = blockIdx.x;
    if (b < nbN) {
        int i = b * blockDim.x + threadIdx.x;
        if (i < n) { g_cnt[i] = 0; g_fill[i] = 0; g_loopsum[i] = 0.f; }
        return;
    }
    if (b == nbN) {
        if (threadIdx.x < 32) {
            int any = 0;
            for (int k = threadIdx.x; k < 512; k += 32) any |= w[2 * k + 1];
            #pragma unroll
            for (int o = 16; o; o >>= 1) any |= __shfl_down_sync(0xFFFFFFFFu, any, o);
            if (threadIdx.x == 0) g_is64 = (any == 0) ? 1 : 0;
        }
        return;
    }
    // c-dots
    __shared__ float s1[128], s2[128];
    int t = threadIdx.x;
    if (t < 128) {
        s1[t] = We1[t] * ae1[t];
        s2[t] = (t < 64) ? We2[t] * ae2[t] : 0.f;
    }
    __syncthreads();
    for (int o = 64; o; o >>= 1) {
        if (t < o) { s1[t] += s1[t + o]; s2[t] += s2[t + o]; }
        __syncthreads();
    }
    if (t == 0) { g_c[0] = s1[0]; g_c[1] = s2[0]; }
}

// ---------------- edge decode (shared by conv_hist / csr_fill) ----------------
__device__ __forceinline__ void decode_edge(const int* __restrict__ w, int e, int E, int N,
                                            int& s, int& d) {
    if (g_is64) {
        const long long* w64 = (const long long*)w;
        s = (int)w64[e];
        d = (int)w64[(size_t)E + e];
    } else {
        s = w[e];
        d = w[(size_t)E + e];
    }
    s = clampi(s, 0, N - 1);
    d = clampi(d, 0, N - 1);
}

// ---------------- degree histogram + loop attr sum ----------------
__global__ void conv_hist(const int* __restrict__ w, const float* __restrict__ ea, int E, int N) {
    int e = blockIdx.x * blockDim.x + threadIdx.x;
    if (e >= E) return;
    int s, d;
    decode_edge(w, e, E, N, s, d);
    atomicAdd(&g_cnt[d], 1);
    atomicAdd(&g_loopsum[d], ea[e]);
}

// ---------------- scan1 (+ fused loop_attr) / scan2 ----------------
__global__ void scan1(int n) {
    __shared__ int s[256];
    int t = threadIdx.x;
    int i = blockIdx.x * 256 + t;
    int v = (i < n) ? g_cnt[i] : 0;
    if (i < n) g_loopattr[i] = g_loopsum[i] / fmaxf((float)v, 1.f);
    s[t] = v;
    __syncthreads();
    #pragma unroll
    for (int o = 1; o < 256; o <<= 1) {
        int y = (t >= o) ? s[t - o] : 0;
        __syncthreads();
        s[t] += y;
        __syncthreads();
    }
    if (i < n) g_rowstart[i] = s[t] - v;   // exclusive, pre block-offset
    if (t == 255) g_bsum[blockIdx.x] = s[255];
}
__global__ void scan2(int nb) {
    __shared__ int s[1024];
    int t = threadIdx.x;
    int v = (t < nb) ? g_bsum[t] : 0;
    s[t] = v;
    __syncthreads();
    #pragma unroll
    for (int o = 1; o < 1024; o <<= 1) {
        int y = (t >= o) ? s[t - o] : 0;
        __syncthreads();
        s[t] += y;
        __syncthreads();
    }
    if (t < nb) g_bsum[t] = s[t] - v;      // exclusive block offsets
}

// ---------------- CSR fill (decodes edges directly, adds block offset) ----------------
__global__ void csr_fill(const int* __restrict__ w, const float* __restrict__ ea, int E, int N) {
    int e = blockIdx.x * blockDim.x + threadIdx.x;
    if (e >= E) return;
    int s, d;
    decode_edge(w, e, E, N, s, d);
    int pos = g_rowstart[d] + g_bsum[d >> 8] + atomicAdd(&g_fill[d], 1);
    EdgeRec r;
    r.src = s;
    r.ea = ea[e];
    g_epack[pos] = r;
}

// ---------------- f32x2 GEMM: g_xh[N,F] = half(A[N,128] @ W[128,F]), fused att dots ----------------
template <int F, bool A_IS_H1>
__global__ __launch_bounds__(256) void gemm_f2(const float* __restrict__ Ain,
                                               const float* __restrict__ W,
                                               const float* __restrict__ atts,
                                               const float* __restrict__ attd,
                                               int N) {
    const float* A = A_IS_H1 ? (const float*)g_h1 : Ain;
    constexpr int BM = 128, BK = 16;
    constexpr int CJ = F / 16;    // cols per thread: 8 (F=128) or 4 (F=64)
    constexpr int CJ2 = CJ / 2;   // col pairs: 4 or 2
    __shared__ float As[BK][BM];
    __shared__ float Ws[BK][F];
    const int tid = threadIdx.x;
    const int tx = tid & 15;
    const int ty = tid >> 4;
    const int row0 = blockIdx.x * BM;

    ull acc[8][CJ2];
    #pragma unroll
    for (int i = 0; i < 8; i++)
        #pragma unroll
        for (int j = 0; j < CJ2; j++) acc[i][j] = 0ull;

    for (int kb = 0; kb < 128; kb += BK) {
        // stage A chunk (BM x BK), transposed: As[k][r]
        #pragma unroll
        for (int q = 0; q < 2; q++) {
            int f4 = tid * 2 + q;
            int r = f4 >> 2, c4 = f4 & 3;
            float4 v = make_float4(0.f, 0.f, 0.f, 0.f);
            if (row0 + r < N)
                v = *(const float4*)&A[(size_t)(row0 + r) * 128 + kb + c4 * 4];
            As[c4 * 4 + 0][r] = v.x;
            As[c4 * 4 + 1][r] = v.y;
            As[c4 * 4 + 2][r] = v.z;
            As[c4 * 4 + 3][r] = v.w;
        }
        // stage W chunk (BK x F), row-major
        constexpr int NF4 = BK * F / 4;            // 512 (F=128) or 256 (F=64)
        #pragma unroll
        for (int q = 0; q < NF4 / 256; q++) {
            int f4 = tid + q * 256;
            int k = f4 / (F / 4);
            int c = (f4 % (F / 4)) * 4;
            *(float4*)&Ws[k][c] = *(const float4*)&W[(size_t)(kb + k) * F + c];
        }
        __syncthreads();
        #pragma unroll
        for (int k = 0; k < BK; k++) {
            float4 a0 = *(const float4*)&As[k][ty * 8];
            float4 a1 = *(const float4*)&As[k][ty * 8 + 4];
            ull a2[8];
            a2[0] = pack_dup(a0.x); a2[1] = pack_dup(a0.y);
            a2[2] = pack_dup(a0.z); a2[3] = pack_dup(a0.w);
            a2[4] = pack_dup(a1.x); a2[5] = pack_dup(a1.y);
            a2[6] = pack_dup(a1.z); a2[7] = pack_dup(a1.w);
            ull b2[CJ2];
            #pragma unroll
            for (int j = 0; j < CJ2; j += 2) {
                ulonglong2 bv = *(const ulonglong2*)&Ws[k][tx * CJ + j * 2];
                b2[j] = bv.x;
                b2[j + 1] = bv.y;
            }
            #pragma unroll
            for (int i = 0; i < 8; i++)
                #pragma unroll
                for (int j = 0; j < CJ2; j++)
                    fma_f32x2(acc[i][j], a2[i], b2[j], acc[i][j]);
        }
        __syncthreads();
    }

    // epilogue: fp32 att dots + fp16 feature store
    float asv[CJ], adv[CJ];
    #pragma unroll
    for (int j = 0; j < CJ; j++) {
        asv[j] = __ldg(&atts[tx * CJ + j]);
        adv[j] = __ldg(&attd[tx * CJ + j]);
    }
    #pragma unroll
    for (int i = 0; i < 8; i++) {
        int r = row0 + ty * 8 + i;
        if (r >= N) break;
        float c8[CJ];
        #pragma unroll
        for (int j = 0; j < CJ2; j++) unpack2(c8[2 * j], c8[2 * j + 1], acc[i][j]);
        float s = 0.f, d = 0.f;
        #pragma unroll
        for (int j = 0; j < CJ; j++) { s += c8[j] * asv[j]; d += c8[j] * adv[j]; }
        #pragma unroll
        for (int o = 8; o; o >>= 1) {
            s += __shfl_down_sync(0xFFFFFFFFu, s, o, 16);
            d += __shfl_down_sync(0xFFFFFFFFu, d, o, 16);
        }
        if (tx == 0) { g_asrc[r] = s; g_adst[r] = d; }
        uint32_t hw[CJ2];
        #pragma unroll
        for (int j = 0; j < CJ2; j++) {
            __half2 h = __floats2half2_rn(c8[2 * j], c8[2 * j + 1]);
            hw[j] = *(uint32_t*)&h;
        }
        __half* dst = &g_xh[(size_t)r * F + tx * CJ];
        if (CJ2 == 4) *(uint4*)dst = make_uint4(hw[0], hw[1], hw[2], hw[3]);
        else          *(uint2*)dst = make_uint2(hw[0], hw[1]);
    }
}

// ---------------- feature load helper (fp16 -> fp32) ----------------
template <int VE>
__device__ __forceinline__ void load_feat(float* v, const __half* p) {
    if (VE == 4) {
        uint2 u = *(const uint2*)p;
        float2 f0 = __half22float2(*(const __half2*)&u.x);
        float2 f1 = __half22float2(*(const __half2*)&u.y);
        v[0] = f0.x; v[1] = f0.y; v[2] = f1.x; v[3] = f1.y;
    } else {
        uint32_t u = *(const uint32_t*)p;
        float2 f0 = __half22float2(*(const __half2*)&u);
        v[0] = f0.x; v[1] = f0.y;
    }
}

// ---------------- fused GAT: online softmax + fp16 gather, unroll-4 MLP ----------------
template <int F, bool OUT_IS_H1>
__global__ void fused_gat(const float* __restrict__ bias, const float* __restrict__ prelu_a,
                          float* __restrict__ outp, int N, int layer) {
    int w = (blockIdx.x * blockDim.x + threadIdx.x) >> 5;
    int lane = threadIdx.x & 31;
    if (w >= N) return;
    float* out = OUT_IS_H1 ? (float*)g_h1 : outp;
    constexpr int VE = F / 32;   // 4 (F=128) or 2 (F=64)
    const float c = g_c[layer];
    const float adst = g_adst[w];
    const float lself = leaky(g_asrc[w] + adst + c * g_loopattr[w]);

    float m = lself, den = 1.f;
    float acc[VE];
    load_feat<VE>(acc, g_xh + (size_t)w * F + lane * VE);  // self-loop, p=1 at m=lself

    const int beg = g_rowstart[w] + g_bsum[w >> 8];
    const int cnt = g_cnt[w];

    #define GAT_UPD(lv, vv)                                             \
        if (lv <= m) {                                                  \
            float p = __expf(lv - m);                                   \
            den += p;                                                   \
            _Pragma("unroll")                                           \
            for (int q = 0; q < VE; q++) acc[q] += p * vv[q];           \
        } else {                                                        \
            float sc = __expf(m - lv);                                  \
            den = den * sc + 1.f;                                       \
            _Pragma("unroll")                                           \
            for (int q = 0; q < VE; q++) acc[q] = acc[q] * sc + vv[q];  \
            m = lv;                                                     \
        }

    int j = 0;
    for (; j + 4 <= cnt; j += 4) {
        // batched loads first (MLP), math after
        EdgeRec e0 = g_epack[beg + j];
        EdgeRec e1 = g_epack[beg + j + 1];
        EdgeRec e2 = g_epack[beg + j + 2];
        EdgeRec e3 = g_epack[beg + j + 3];
        float a0 = g_asrc[e0.src], a1 = g_asrc[e1.src];
        float a2 = g_asrc[e2.src], a3 = g_asrc[e3.src];
        float v0[VE], v1[VE], v2[VE], v3[VE];
        load_feat<VE>(v0, g_xh + (size_t)e0.src * F + lane * VE);
        load_feat<VE>(v1, g_xh + (size_t)e1.src * F + lane * VE);
        load_feat<VE>(v2, g_xh + (size_t)e2.src * F + lane * VE);
        load_feat<VE>(v3, g_xh + (size_t)e3.src * F + lane * VE);
        float l0 = leaky(a0 + adst + c * e0.ea);
        float l1 = leaky(a1 + adst + c * e1.ea);
        float l2 = leaky(a2 + adst + c * e2.ea);
        float l3 = leaky(a3 + adst + c * e3.ea);
        GAT_UPD(l0, v0);
        GAT_UPD(l1, v1);
        GAT_UPD(l2, v2);
        GAT_UPD(l3, v3);
    }
    for (; j < cnt; j++) {
        EdgeRec er = g_epack[beg + j];
        float l = leaky(g_asrc[er.src] + adst + c * er.ea);
        float v[VE];
        load_feat<VE>(v, g_xh + (size_t)er.src * F + lane * VE);
        GAT_UPD(l, v);
    }
    #undef GAT_UPD

    float inv = 1.f / den;
    float a = *prelu_a;
    #pragma unroll
    for (int q = 0; q < VE; q++) {
        float o = acc[q] * inv + bias[lane * VE + q];
        out[(size_t)w * F + lane * VE + q] = o > 0.f ? o : a * o;
    }
}

extern "C" void kernel_launch(void* const* d_in, const int* in_sizes, int n_in,
                              void* d_out, int out_size) {
    const float*      x    = (const float*)d_in[0];
    const int*        eiw  = (const int*)d_in[1];   // edge_index as 32-bit words
    const float*      ea   = (const float*)d_in[2];
    const float*      W1   = (const float*)d_in[3];
    const float*      as1  = (const float*)d_in[4];
    const float*      ad1  = (const float*)d_in[5];
    const float*      We1  = (const float*)d_in[6];
    const float*      ae1  = (const float*)d_in[7];
    const float*      b1   = (const float*)d_in[8];
    const float*      W2   = (const float*)d_in[9];
    const float*      as2  = (const float*)d_in[10];
    const float*      ad2  = (const float*)d_in[11];
    const float*      We2  = (const float*)d_in[12];
    const float*      ae2  = (const float*)d_in[13];
    const float*      b2   = (const float*)d_in[14];
    const float*      pa   = (const float*)d_in[15];
    float*            out  = (float*)d_out;

    const int N = in_sizes[0] / DIN;
    const int E = in_sizes[1] / 2;

    const int TB = 256;
    int nb_N   = (N + TB - 1) / TB;       // 391 for N=100000
    int nb_E   = (E + TB - 1) / TB;
    int nb_att = ((N * 32) + TB - 1) / TB;
    int nb_gemm = (N + 127) / 128;

    // Launch order places gemm_f2<H1> at my-launch #4 so ncu (-s 5 -c 1, with
    // ~2 harness launches ahead of ours) profiles it. GEMM1 depends only on x/W1.
    prep_misc<<<nb_N + 2, TB>>>(eiw, We1, ae1, We2, ae2, N, nb_N);   // 1
    conv_hist<<<nb_E, TB>>>(eiw, ea, E, N);                          // 2
    scan1<<<nb_N, 256>>>(N);                                         // 3
    gemm_f2<H1, false><<<nb_gemm, 256>>>(x, W1, as1, ad1, N);        // 4  <- profile target
    scan2<<<1, 1024>>>(nb_N);                                        // 5
    csr_fill<<<nb_E, TB>>>(eiw, ea, E, N);                           // 6
    fused_gat<H1, true><<<nb_att, TB>>>(b1, pa, out, N, 0);          // 7
    gemm_f2<H2, true><<<nb_gemm, 256>>>(nullptr, W2, as2, ad2, N);   // 8
    fused_gat<H2, false><<<nb_att, TB>>>(b2, pa, out, N, 1);         // 9
}

// round 10
// speedup vs baseline: 1.3122x; 1.0632x over previous
#include <cuda_runtime.h>
#include <cuda_fp16.h>
#include <cstdint>

// ---------------- problem constants ----------------
#define NNODES 100000
#define NEDGES 1600000
#define DIN 128
#define H1 128
#define H2 64
#define NEG_SLOPE 0.2f

typedef unsigned long long ull;

// ---------------- device scratch (no allocations allowed) ----------------
static __device__ __align__(16) __half g_xh[(size_t)NNODES * 128]; // fp16 xl (gather source)
static __device__ __align__(16) float  g_h1[(size_t)NNODES * 128]; // layer-1 output (fp32)
static __device__ float    g_asrc[NNODES];
static __device__ float    g_adst[NNODES];
static __device__ float    g_loopsum[NNODES];
static __device__ float    g_loopattr[NNODES];
static __device__ int      g_cnt[NNODES];       // in-degree
static __device__ int      g_rowstart[NNODES];  // CSR row offsets (pre block-offset)
static __device__ int      g_fill[NNODES];      // fill cursors
static __device__ int      g_bsum[1024];        // scan block sums

struct __align__(8) EdgeRec { int src; float ea; };
static __device__ EdgeRec  g_epack[NEDGES];     // CSR: (src, edge_attr) per slot
static __device__ float    g_c[2];              // dot(W_edge, att_edge) per layer
static __device__ int      g_is64;              // edge_index dtype flag

// ---------------- helpers ----------------
__device__ __forceinline__ float leaky(float x) {
    return x >= 0.f ? x : NEG_SLOPE * x;
}
__device__ __forceinline__ int clampi(int v, int lo, int hi) {
    return v < lo ? lo : (v > hi ? hi : v);
}
// packed fp32x2 FMA (SASS FFMA2) — exact fp32 on both halves, 2x issue density
__device__ __forceinline__ void fma_f32x2(ull& d, ull a, ull b, ull c) {
    asm("fma.rn.f32x2 %0, %1, %2, %3;" : "=l"(d) : "l"(a), "l"(b), "l"(c));
}
__device__ __forceinline__ ull pack_dup(float x) {
    ull r;
    asm("mov.b64 %0, {%1, %1};" : "=l"(r) : "f"(x));
    return r;
}
__device__ __forceinline__ void unpack2(float& lo, float& hi, ull v) {
    asm("mov.b64 {%0, %1}, %2;" : "=f"(lo), "=f"(hi) : "l"(v));
}
// 16B async copy global -> shared (LDGSTS)
__device__ __forceinline__ void cp_async16(uint32_t saddr, const void* gptr) {
    asm volatile("cp.async.cg.shared.global [%0], [%1], 16;" :: "r"(saddr), "l"(gptr));
}
__device__ __forceinline__ void cp_commit() {
    asm volatile("cp.async.commit_group;");
}
__device__ __forceinline__ void cp_wait0() {
    asm volatile("cp.async.wait_group 0;" ::: "memory");
}

// ---------------- fused prep: zero counters / detect dtype / calc c's ----------------
__global__ void prep_misc(const int* __restrict__ w,
                          const float* __restrict__ We1, const float* __restrict__ ae1,
                          const float* __restrict__ We2, const float* __restrict__ ae2,
                          int n, int nbN) {
    int b = blockIdx.x;
    if (b < nbN) {
        int i = b * blockDim.x + threadIdx.x;
        if (i < n) { g_cnt[i] = 0; g_fill[i] = 0; g_loopsum[i] = 0.f; }
        return;
    }
    if (b == nbN) {
        if (threadIdx.x < 32) {
            int any = 0;
            for (int k = threadIdx.x; k < 512; k += 32) any |= w[2 * k + 1];
            #pragma unroll
            for (int o = 16; o; o >>= 1) any |= __shfl_down_sync(0xFFFFFFFFu, any, o);
            if (threadIdx.x == 0) g_is64 = (any == 0) ? 1 : 0;
        }
        return;
    }
    __shared__ float s1[128], s2[128];
    int t = threadIdx.x;
    if (t < 128) {
        s1[t] = We1[t] * ae1[t];
        s2[t] = (t < 64) ? We2[t] * ae2[t] : 0.f;
    }
    __syncthreads();
    for (int o = 64; o; o >>= 1) {
        if (t < o) { s1[t] += s1[t + o]; s2[t] += s2[t + o]; }
        __syncthreads();
    }
    if (t == 0) { g_c[0] = s1[0]; g_c[1] = s2[0]; }
}

// ---------------- edge decode ----------------
__device__ __forceinline__ void decode_edge(const int* __restrict__ w, int e, int E, int N,
                                            int& s, int& d) {
    if (g_is64) {
        const long long* w64 = (const long long*)w;
        s = (int)w64[e];
        d = (int)w64[(size_t)E + e];
    } else {
        s = w[e];
        d = w[(size_t)E + e];
    }
    s = clampi(s, 0, N - 1);
    d = clampi(d, 0, N - 1);
}

// ---------------- degree histogram + loop attr sum ----------------
__global__ void conv_hist(const int* __restrict__ w, const float* __restrict__ ea, int E, int N) {
    int e = blockIdx.x * blockDim.x + threadIdx.x;
    if (e >= E) return;
    int s, d;
    decode_edge(w, e, E, N, s, d);
    atomicAdd(&g_cnt[d], 1);
    atomicAdd(&g_loopsum[d], ea[e]);
}

// ---------------- scan1 (+ fused loop_attr) / scan2 ----------------
__global__ void scan1(int n) {
    __shared__ int s[256];
    int t = threadIdx.x;
    int i = blockIdx.x * 256 + t;
    int v = (i < n) ? g_cnt[i] : 0;
    if (i < n) g_loopattr[i] = g_loopsum[i] / fmaxf((float)v, 1.f);
    s[t] = v;
    __syncthreads();
    #pragma unroll
    for (int o = 1; o < 256; o <<= 1) {
        int y = (t >= o) ? s[t - o] : 0;
        __syncthreads();
        s[t] += y;
        __syncthreads();
    }
    if (i < n) g_rowstart[i] = s[t] - v;
    if (t == 255) g_bsum[blockIdx.x] = s[255];
}
__global__ void scan2(int nb) {
    __shared__ int s[1024];
    int t = threadIdx.x;
    int v = (t < nb) ? g_bsum[t] : 0;
    s[t] = v;
    __syncthreads();
    #pragma unroll
    for (int o = 1; o < 1024; o <<= 1) {
        int y = (t >= o) ? s[t - o] : 0;
        __syncthreads();
        s[t] += y;
        __syncthreads();
    }
    if (t < nb) g_bsum[t] = s[t] - v;
}

// ---------------- CSR fill ----------------
__global__ void csr_fill(const int* __restrict__ w, const float* __restrict__ ea, int E, int N) {
    int e = blockIdx.x * blockDim.x + threadIdx.x;
    if (e >= E) return;
    int s, d;
    decode_edge(w, e, E, N, s, d);
    int pos = g_rowstart[d] + g_bsum[d >> 8] + atomicAdd(&g_fill[d], 1);
    EdgeRec r;
    r.src = s;
    r.ea = ea[e];
    g_epack[pos] = r;
}

// ---------------- pipelined f32x2 GEMM ----------------
// 128 threads, BM=64, BN=F, BK=16; 8x8 thread tile; double-buffered smem:
// W via cp.async, A via register prefetch (needs transpose). One sync per step.
template <int F, bool A_IS_H1>
__global__ __launch_bounds__(128) void gemm_f2(const float* __restrict__ Ain,
                                               const float* __restrict__ W,
                                               const float* __restrict__ atts,
                                               const float* __restrict__ attd,
                                               int N) {
    const float* A = A_IS_H1 ? (const float*)g_h1 : Ain;
    constexpr int BM = 64, BK = 16;
    constexpr int CJ = F / 16;    // cols per thread: 8 (F=128) or 4 (F=64)
    constexpr int CJ2 = CJ / 2;   // ull pairs: 4 or 2
    __shared__ __align__(16) float As[2][BK][BM];   // 2 x 4KB
    __shared__ __align__(16) float Ws[2][BK][F];    // 2 x 8KB (F=128) / 4KB
    const int tid = threadIdx.x;
    const int tx = tid & 15;
    const int ty = tid >> 4;      // 0..7
    const int row0 = blockIdx.x * BM;

    const uint32_t ws_s0 = (uint32_t)__cvta_generic_to_shared(&Ws[0][0][0]);
    const uint32_t ws_s1 = (uint32_t)__cvta_generic_to_shared(&Ws[1][0][0]);

    // A-prefetch thread mapping: f4 = tid*2+q -> row r=f4>>2, k-chunk c4=f4&3
    const int pr0 = (tid * 2) >> 2, pc0 = (tid * 2) & 3;
    const int pr1 = (tid * 2 + 1) >> 2, pc1 = (tid * 2 + 1) & 3;

    ull acc[8][CJ2];
    #pragma unroll
    for (int i = 0; i < 8; i++)
        #pragma unroll
        for (int j = 0; j < CJ2; j++) acc[i][j] = 0ull;

    // ---- stage helpers (inlined manually) ----
    constexpr int NW16 = BK * F * 4 / 16;           // 16B chunks in W tile: 512(F=128)/256
    constexpr int WCH = NW16 / 128;                 // per-thread chunks: 4 / 2

    // prologue: stage kb=0 into buffer 0
    {
        float4 p0 = make_float4(0.f, 0.f, 0.f, 0.f), p1 = p0;
        if (row0 + pr0 < N) p0 = *(const float4*)&A[(size_t)(row0 + pr0) * 128 + pc0 * 4];
        if (row0 + pr1 < N) p1 = *(const float4*)&A[(size_t)(row0 + pr1) * 128 + pc1 * 4];
        #pragma unroll
        for (int q = 0; q < WCH; q++) {
            int f4 = tid + q * 128;
            int k = f4 / (F / 4);
            int c = (f4 % (F / 4)) * 4;
            cp_async16(ws_s0 + (uint32_t)(k * F + c) * 4, &W[(size_t)k * F + c]);
        }
        cp_commit();
        As[0][pc0 * 4 + 0][pr0] = p0.x; As[0][pc0 * 4 + 1][pr0] = p0.y;
        As[0][pc0 * 4 + 2][pr0] = p0.z; As[0][pc0 * 4 + 3][pr0] = p0.w;
        As[0][pc1 * 4 + 0][pr1] = p1.x; As[0][pc1 * 4 + 1][pr1] = p1.y;
        As[0][pc1 * 4 + 2][pr1] = p1.z; As[0][pc1 * 4 + 3][pr1] = p1.w;
        cp_wait0();
        __syncthreads();
    }

    int buf = 0;
    for (int kb = BK; kb <= 128; kb += BK) {
        // prefetch next tile (if any) while computing current
        float4 p0, p1;
        bool more = (kb < 128);
        if (more) {
            p0 = make_float4(0.f, 0.f, 0.f, 0.f); p1 = p0;
            if (row0 + pr0 < N) p0 = *(const float4*)&A[(size_t)(row0 + pr0) * 128 + kb + pc0 * 4];
            if (row0 + pr1 < N) p1 = *(const float4*)&A[(size_t)(row0 + pr1) * 128 + kb + pc1 * 4];
            uint32_t wsn = (buf ? ws_s0 : ws_s1);
            #pragma unroll
            for (int q = 0; q < WCH; q++) {
                int f4 = tid + q * 128;
                int k = f4 / (F / 4);
                int c = (f4 % (F / 4)) * 4;
                cp_async16(wsn + (uint32_t)(k * F + c) * 4, &W[(size_t)(kb + k) * F + c]);
            }
            cp_commit();
        }
        // compute on current buffer
        #pragma unroll
        for (int k = 0; k < BK; k++) {
            float4 a0 = *(const float4*)&As[buf][k][ty * 8];
            float4 a1 = *(const float4*)&As[buf][k][ty * 8 + 4];
            ull a2[8];
            a2[0] = pack_dup(a0.x); a2[1] = pack_dup(a0.y);
            a2[2] = pack_dup(a0.z); a2[3] = pack_dup(a0.w);
            a2[4] = pack_dup(a1.x); a2[5] = pack_dup(a1.y);
            a2[6] = pack_dup(a1.z); a2[7] = pack_dup(a1.w);
            ull b2[CJ2];
            #pragma unroll
            for (int j = 0; j < CJ2; j += 2) {
                ulonglong2 bv = *(const ulonglong2*)&Ws[buf][k][tx * CJ + j * 2];
                b2[j] = bv.x;
                b2[j + 1] = bv.y;
            }
            #pragma unroll
            for (int i = 0; i < 8; i++)
                #pragma unroll
                for (int j = 0; j < CJ2; j++)
                    fma_f32x2(acc[i][j], a2[i], b2[j], acc[i][j]);
        }
        if (more) {
            int nb = buf ^ 1;
            As[nb][pc0 * 4 + 0][pr0] = p0.x; As[nb][pc0 * 4 + 1][pr0] = p0.y;
            As[nb][pc0 * 4 + 2][pr0] = p0.z; As[nb][pc0 * 4 + 3][pr0] = p0.w;
            As[nb][pc1 * 4 + 0][pr1] = p1.x; As[nb][pc1 * 4 + 1][pr1] = p1.y;
            As[nb][pc1 * 4 + 2][pr1] = p1.z; As[nb][pc1 * 4 + 3][pr1] = p1.w;
            cp_wait0();
            __syncthreads();
            buf = nb;
        }
    }

    // epilogue: fp32 att dots + fp16 feature store
    float asv[CJ], adv[CJ];
    #pragma unroll
    for (int j = 0; j < CJ; j++) {
        asv[j] = __ldg(&atts[tx * CJ + j]);
        adv[j] = __ldg(&attd[tx * CJ + j]);
    }
    #pragma unroll
    for (int i = 0; i < 8; i++) {
        int r = row0 + ty * 8 + i;
        if (r >= N) break;
        float c8[CJ];
        #pragma unroll
        for (int j = 0; j < CJ2; j++) unpack2(c8[2 * j], c8[2 * j + 1], acc[i][j]);
        float s = 0.f, d = 0.f;
        #pragma unroll
        for (int j = 0; j < CJ; j++) { s += c8[j] * asv[j]; d += c8[j] * adv[j]; }
        #pragma unroll
        for (int o = 8; o; o >>= 1) {
            s += __shfl_down_sync(0xFFFFFFFFu, s, o, 16);
            d += __shfl_down_sync(0xFFFFFFFFu, d, o, 16);
        }
        if (tx == 0) { g_asrc[r] = s; g_adst[r] = d; }
        uint32_t hw[CJ2];
        #pragma unroll
        for (int j = 0; j < CJ2; j++) {
            __half2 h = __floats2half2_rn(c8[2 * j], c8[2 * j + 1]);
            hw[j] = *(uint32_t*)&h;
        }
        __half* dst = &g_xh[(size_t)r * F + tx * CJ];
        if (CJ2 == 4) *(uint4*)dst = make_uint4(hw[0], hw[1], hw[2], hw[3]);
        else          *(uint2*)dst = make_uint2(hw[0], hw[1]);
    }
}

// ---------------- feature load helper (fp16 -> fp32) ----------------
template <int VE>
__device__ __forceinline__ void load_feat(float* v, const __half* p) {
    if (VE == 4) {
        uint2 u = *(const uint2*)p;
        float2 f0 = __half22float2(*(const __half2*)&u.x);
        float2 f1 = __half22float2(*(const __half2*)&u.y);
        v[0] = f0.x; v[1] = f0.y; v[2] = f1.x; v[3] = f1.y;
    } else {
        uint32_t u = *(const uint32_t*)p;
        float2 f0 = __half22float2(*(const __half2*)&u);
        v[0] = f0.x; v[1] = f0.y;
    }
}

// ---------------- fused GAT: online softmax + fp16 gather, unroll-4 MLP ----------------
template <int F, bool OUT_IS_H1>
__global__ void fused_gat(const float* __restrict__ bias, const float* __restrict__ prelu_a,
                          float* __restrict__ outp, int N, int layer) {
    int w = (blockIdx.x * blockDim.x + threadIdx.x) >> 5;
    int lane = threadIdx.x & 31;
    if (w >= N) return;
    float* out = OUT_IS_H1 ? (float*)g_h1 : outp;
    constexpr int VE = F / 32;
    const float c = g_c[layer];
    const float adst = g_adst[w];
    const float lself = leaky(g_asrc[w] + adst + c * g_loopattr[w]);

    float m = lself, den = 1.f;
    float acc[VE];
    load_feat<VE>(acc, g_xh + (size_t)w * F + lane * VE);

    const int beg = g_rowstart[w] + g_bsum[w >> 8];
    const int cnt = g_cnt[w];

    #define GAT_UPD(lv, vv)                                             \
        if (lv <= m) {                                                  \
            float p = __expf(lv - m);                                   \
            den += p;                                                   \
            _Pragma("unroll")                                           \
            for (int q = 0; q < VE; q++) acc[q] += p * vv[q];           \
        } else {                                                        \
            float sc = __expf(m - lv);                                  \
            den = den * sc + 1.f;                                       \
            _Pragma("unroll")                                           \
            for (int q = 0; q < VE; q++) acc[q] = acc[q] * sc + vv[q];  \
            m = lv;                                                     \
        }

    int j = 0;
    for (; j + 4 <= cnt; j += 4) {
        EdgeRec e0 = g_epack[beg + j];
        EdgeRec e1 = g_epack[beg + j + 1];
        EdgeRec e2 = g_epack[beg + j + 2];
        EdgeRec e3 = g_epack[beg + j + 3];
        float a0 = g_asrc[e0.src], a1 = g_asrc[e1.src];
        float a2 = g_asrc[e2.src], a3 = g_asrc[e3.src];
        float v0[VE], v1[VE], v2[VE], v3[VE];
        load_feat<VE>(v0, g_xh + (size_t)e0.src * F + lane * VE);
        load_feat<VE>(v1, g_xh + (size_t)e1.src * F + lane * VE);
        load_feat<VE>(v2, g_xh + (size_t)e2.src * F + lane * VE);
        load_feat<VE>(v3, g_xh + (size_t)e3.src * F + lane * VE);
        float l0 = leaky(a0 + adst + c * e0.ea);
        float l1 = leaky(a1 + adst + c * e1.ea);
        float l2 = leaky(a2 + adst + c * e2.ea);
        float l3 = leaky(a3 + adst + c * e3.ea);
        GAT_UPD(l0, v0);
        GAT_UPD(l1, v1);
        GAT_UPD(l2, v2);
        GAT_UPD(l3, v3);
    }
    for (; j < cnt; j++) {
        EdgeRec er = g_epack[beg + j];
        float l = leaky(g_asrc[er.src] + adst + c * er.ea);
        float v[VE];
        load_feat<VE>(v, g_xh + (size_t)er.src * F + lane * VE);
        GAT_UPD(l, v);
    }
    #undef GAT_UPD

    float inv = 1.f / den;
    float a = *prelu_a;
    #pragma unroll
    for (int q = 0; q < VE; q++) {
        float o = acc[q] * inv + bias[lane * VE + q];
        out[(size_t)w * F + lane * VE + q] = o > 0.f ? o : a * o;
    }
}

extern "C" void kernel_launch(void* const* d_in, const int* in_sizes, int n_in,
                              void* d_out, int out_size) {
    const float*      x    = (const float*)d_in[0];
    const int*        eiw  = (const int*)d_in[1];
    const float*      ea   = (const float*)d_in[2];
    const float*      W1   = (const float*)d_in[3];
    const float*      as1  = (const float*)d_in[4];
    const float*      ad1  = (const float*)d_in[5];
    const float*      We1  = (const float*)d_in[6];
    const float*      ae1  = (const float*)d_in[7];
    const float*      b1   = (const float*)d_in[8];
    const float*      W2   = (const float*)d_in[9];
    const float*      as2  = (const float*)d_in[10];
    const float*      ad2  = (const float*)d_in[11];
    const float*      We2  = (const float*)d_in[12];
    const float*      ae2  = (const float*)d_in[13];
    const float*      b2   = (const float*)d_in[14];
    const float*      pa   = (const float*)d_in[15];
    float*            out  = (float*)d_out;

    const int N = in_sizes[0] / DIN;
    const int E = in_sizes[1] / 2;

    const int TB = 256;
    int nb_N   = (N + TB - 1) / TB;
    int nb_E   = (E + TB - 1) / TB;
    int nb_att = ((N * 32) + TB - 1) / TB;
    int nb_gemm = (N + 63) / 64;

    // gemm1 stays at my-launch #4 (ncu -s 5 profile target)
    prep_misc<<<nb_N + 2, TB>>>(eiw, We1, ae1, We2, ae2, N, nb_N);   // 1
    conv_hist<<<nb_E, TB>>>(eiw, ea, E, N);                          // 2
    scan1<<<nb_N, 256>>>(N);                                         // 3
    gemm_f2<H1, false><<<nb_gemm, 128>>>(x, W1, as1, ad1, N);        // 4
    scan2<<<1, 1024>>>(nb_N);                                        // 5
    csr_fill<<<nb_E, TB>>>(eiw, ea, E, N);                           // 6
    fused_gat<H1, true><<<nb_att, TB>>>(b1, pa, out, N, 0);          // 7
    gemm_f2<H2, true><<<nb_gemm, 128>>>(nullptr, W2, as2, ad2, N);   // 8
    fused_gat<H2, false><<<nb_att, TB>>>(b2, pa, out, N, 1);         // 9
}